// round 16
// baseline (speedup 1.0000x reference)
#include <cuda_runtime.h>
#include <cuda_fp16.h>
#include <cstdint>

// Problem constants
#define B_     64
#define H_     512
#define W_     512
#define C_     3
#define G_     64
#define K_     3
#define D_IN   (K_*G_*G_*C_)   // 36864
#define HG_    128
#define HL_    128

// GEMM split-K config
#define NCHUNK 144
#define DC     256             // K-dims per CTA chunk (NCHUNK*DC == D_IN)

// Scratch (device globals)
__device__ __half g_phi[(size_t)B_ * D_IN];           // 4.7 MB (single fp16)
__device__ __half g_W1h[(size_t)D_IN * HG_];          // 9.4 MB (fp16 W1, [k][n])
__device__ float g_part[(size_t)NCHUNK * B_ * HG_];   // 4.7 MB

__device__ __forceinline__ uint32_t smem_u32(const void* p) {
    uint32_t a;
    asm("{ .reg .u64 t; cvta.to.shared.u64 t, %1; cvt.u32.u64 %0, t; }"
        : "=r"(a) : "l"(p));
    return a;
}
__device__ __forceinline__ void cp16(uint32_t dst, const void* src) {
    asm volatile("cp.async.cg.shared.global [%0], [%1], 16;"
                 :: "r"(dst), "l"(src) : "memory");
}
#define CP_COMMIT() asm volatile("cp.async.commit_group;" ::: "memory")

// ---------------------------------------------------------------------------
// Kernel 1: fused extraction + pooling — TWO gy2 windows per block.
// Stages 8 contiguous source rows with the measured-best scalar style,
// issuing all 32 loads/thread before one sync (2x MLP of the 1-window
// version), then pools both windows. Plus appended W1 fp32->fp16 convert.
// Grid (32, 96): by<64 extract (b=by, windows 2bx, 2bx+1);
//                by>=64 convert chunk (by-64)*32+bx of W1.
// ---------------------------------------------------------------------------
__global__ __launch_bounds__(192) void extract_kernel(
    const float* __restrict__ x, const float* __restrict__ l,
    const float* __restrict__ W1)
{
    const int tid = threadIdx.x;

    if (blockIdx.y >= 64) {
        // ---- W1 convert: 1024 chunks x 4608 elements ----
        const int chunk = (blockIdx.y - 64) * 32 + blockIdx.x;   // 0..1023
        const size_t base = (size_t)chunk * 4608;
        #pragma unroll
        for (int j = 0; j < 6; j++) {
            const size_t idx = base + j * 768 + tid * 4;
            const float4 v = *reinterpret_cast<const float4*>(&W1[idx]);
            __half2 p0; p0.x = __float2half_rn(v.x); p0.y = __float2half_rn(v.y);
            __half2 p1; p1.x = __float2half_rn(v.z); p1.y = __float2half_rn(v.w);
            uint2 out;
            out.x = *reinterpret_cast<uint32_t*>(&p0);
            out.y = *reinterpret_cast<uint32_t*>(&p1);
            *reinterpret_cast<uint2*>(&g_W1h[idx]) = out;
        }
        return;
    }

    __shared__ float buf[8 * 768];     // 24 KB: 8 staged rows

    const int bx  = blockIdx.x;        // 0..31 -> windows 2bx, 2bx+1
    const int b   = blockIdx.y;

    // denormalize coords exactly like reference: trunc((0.5*(l+1))*512)
    const float lx = __ldg(&l[b * 2 + 0]);
    const float ly = __ldg(&l[b * 2 + 1]);
    const int cx = (int)((0.5f * (lx + 1.0f)) * 512.0f);
    const int cy = (int)((0.5f * (ly + 1.0f)) * 512.0f);
    const int xs = cx - 128;
    const int ys = cy - 128 + bx * 8;  // first of 8 contiguous staged rows

    const int jlo = (xs < 0 ? -xs : 0) * 3;
    const int xe  = xs + 256;
    const int jhi = ((xe > W_ ? W_ : xe) - xs) * 3;

    // stage 8 contiguous source rows (zero-filled OOB), scalar loads,
    // all 32 loads per thread in flight before the single sync
    #pragma unroll
    for (int rr = 0; rr < 8; rr++) {
        const int y = ys + rr;
        const bool yok = (y >= 0) && (y < H_);
        const float* rowp = x + (((size_t)b * H_ + y) * W_ + xs) * C_;
        #pragma unroll
        for (int it = 0; it < 4; it++) {
            const int j = tid + it * 192;
            float v = 0.0f;
            if (yok && j >= jlo && j < jhi) v = __ldg(rowp + j);
            buf[rr * 768 + j] = v;
        }
    }
    __syncthreads();

    const int gx = tid / 3;
    const int c  = tid - gx * 3;
    const size_t phiB = (size_t)b * D_IN;

    #pragma unroll
    for (int w = 0; w < 2; w++) {
        const int gy2 = 2 * bx + w;
        const int r0  = 4 * w;                 // staged row base for window w

        // ---- k=2: pool 4x4 ----
        {
            float sum = 0.0f;
            #pragma unroll
            for (int dy = 0; dy < 4; dy++)
                #pragma unroll
                for (int dx = 0; dx < 4; dx++)
                    sum += buf[(r0 + dy) * 768 + (gx * 4 + dx) * 3 + c];
            g_phi[phiB + (2 * G_ + gy2) * (G_ * C_) + tid] =
                __float2half_rn(sum * (1.0f / 16.0f));
        }

        // ---- k=1: two output rows, pool 2x2 over central 128 cols ----
        if (gy2 >= 16 && gy2 < 48) {
            #pragma unroll
            for (int h = 0; h < 2; h++) {
                const int gy1 = 2 * gy2 - 32 + h;
                float sum = 0.0f;
                #pragma unroll
                for (int dy = 0; dy < 2; dy++)
                    #pragma unroll
                    for (int dx = 0; dx < 2; dx++)
                        sum += buf[(r0 + 2 * h + dy) * 768 + (64 + gx * 2 + dx) * 3 + c];
                g_phi[phiB + (G_ + gy1) * (G_ * C_) + tid] =
                    __float2half_rn(sum * 0.25f);
            }
        }

        // ---- k=0: four output rows, direct copy of central 64 cols ----
        if (gy2 >= 24 && gy2 < 40) {
            #pragma unroll
            for (int rr = 0; rr < 4; rr++) {
                const int gy0 = 4 * gy2 - 96 + rr;
                g_phi[phiB + gy0 * (G_ * C_) + tid] =
                    __float2half_rn(buf[(r0 + rr) * 768 + (96 + gx) * 3 + c]);
            }
        }
    }
}

// ---------------------------------------------------------------------------
// Kernel 2: split-K GEMM via mma.sync fp16, single pass, 2-stage cp.async
// pipeline (measured best, R15). B in smem as [k][n], ldmatrix.trans.
// Grid 144, 512 threads (16 warps, warp = 16m x 32n).
// ---------------------------------------------------------------------------
#define KSTR    136                      // A: padded K stride in fp16
#define NPAD    136                      // B: padded N stride in fp16 (272B)
#define A_TILE  (64 * KSTR * 2)          // 17408 B
#define B_TILE  (128 * NPAD * 2)         // 34816 B (128 k-rows)
#define STAGE_B (A_TILE + B_TILE)        // 52224 B per stage
#define SMEM_GEMM (2 * STAGE_B)          // 104448 B

__device__ __forceinline__ void ldsm_x4(uint32_t a[4], uint32_t addr) {
    asm volatile("ldmatrix.sync.aligned.m8n8.x4.shared.b16 {%0,%1,%2,%3}, [%4];"
                 : "=r"(a[0]), "=r"(a[1]), "=r"(a[2]), "=r"(a[3]) : "r"(addr));
}
__device__ __forceinline__ void ldsm_x4t(uint32_t a[4], uint32_t addr) {
    asm volatile("ldmatrix.sync.aligned.m8n8.x4.trans.shared.b16 {%0,%1,%2,%3}, [%4];"
                 : "=r"(a[0]), "=r"(a[1]), "=r"(a[2]), "=r"(a[3]) : "r"(addr));
}
__device__ __forceinline__ void mma_fp16(
    float c[4], const uint32_t a[4], uint32_t b0, uint32_t b1)
{
    asm volatile(
        "mma.sync.aligned.m16n8k16.row.col.f32.f16.f16.f32 "
        "{%0,%1,%2,%3}, {%4,%5,%6,%7}, {%8,%9}, {%0,%1,%2,%3};"
        : "+f"(c[0]), "+f"(c[1]), "+f"(c[2]), "+f"(c[3])
        : "r"(a[0]), "r"(a[1]), "r"(a[2]), "r"(a[3]), "r"(b0), "r"(b1));
}

__global__ __launch_bounds__(512) void gemm_mma_kernel()
{
    extern __shared__ char smem[];
    const uint32_t sb = smem_u32(smem);
    const int tid  = threadIdx.x;
    const int wid  = tid >> 5;
    const int lane = tid & 31;

    const int mt = wid >> 2;     // m16 tile
    const int nq = wid & 3;      // n32 quarter

    const uint32_t aRel = (uint32_t)((mt * 16 + (lane & 15)) * (KSTR * 2)
                                     + (lane >> 4) * 16);
    const uint32_t bRel = (uint32_t)(((lane & 7) + ((lane >> 3) & 1) * 8) * (NPAD * 2)
                                     + (nq * 32 + (lane >> 4) * 8) * 2);

    const int d0 = blockIdx.x * DC;

    auto fill = [&](int stage, int dk) {
        const uint32_t base = sb + stage * STAGE_B;
        #pragma unroll
        for (int it = 0; it < 2; it++) {             // A: 64 rows x 16 chunks
            const int idx = it * 512 + tid;
            const int m = idx >> 4;
            const int i = idx & 15;
            cp16(base + m * (KSTR * 2) + i * 16,
                 &g_phi[(size_t)m * D_IN + dk + i * 8]);
        }
        #pragma unroll
        for (int it = 0; it < 4; it++) {             // B: 128 k-rows x 16 chunks
            const int idx = it * 512 + tid;
            const int k = idx >> 4;
            const int i = idx & 15;
            cp16(base + A_TILE + k * (NPAD * 2) + i * 16,
                 &g_W1h[(size_t)(dk + k) * HG_ + i * 8]);
        }
    };

    float acc[4][4];
    #pragma unroll
    for (int nt = 0; nt < 4; nt++)
        #pragma unroll
        for (int j = 0; j < 4; j++) acc[nt][j] = 0.0f;

    auto compute = [&](int stage) {
        const uint32_t base = sb + stage * STAGE_B;
        const uint32_t aBase = base + aRel;
        const uint32_t bBase = base + A_TILE + bRel;
        #pragma unroll
        for (int kt = 0; kt < 8; kt++) {
            uint32_t a[4];
            ldsm_x4(a, aBase + kt * 32);
            #pragma unroll
            for (int np = 0; np < 2; np++) {
                uint32_t bq[4];
                ldsm_x4t(bq, bBase + kt * 16 * (NPAD * 2) + np * 32);
                mma_fp16(acc[np * 2 + 0], a, bq[0], bq[1]);
                mma_fp16(acc[np * 2 + 1], a, bq[2], bq[3]);
            }
        }
    };

    // ---- 2-stage pipeline ----
    fill(0, d0);        CP_COMMIT();
    fill(1, d0 + 128);  CP_COMMIT();
    asm volatile("cp.async.wait_group 1;" ::: "memory");
    __syncthreads();
    compute(0);
    asm volatile("cp.async.wait_group 0;" ::: "memory");
    __syncthreads();
    compute(1);

    // ---- epilogue: write 64x128 partial tile ----
    float* part = &g_part[(size_t)blockIdx.x * (B_ * HG_)];
    const int qid = lane >> 2;
    const int tq  = lane & 3;
    const int row0 = mt * 16 + qid;
    #pragma unroll
    for (int nt = 0; nt < 4; nt++) {
        const int col = nq * 32 + nt * 8 + tq * 2;
        float2 v0; v0.x = acc[nt][0]; v0.y = acc[nt][1];
        float2 v1; v1.x = acc[nt][2]; v1.y = acc[nt][3];
        *reinterpret_cast<float2*>(part + row0 * HG_ + col) = v0;
        *reinterpret_cast<float2*>(part + (row0 + 8) * HG_ + col) = v1;
    }
}

// ---------------------------------------------------------------------------
// Kernel 3: reduce partials + bias + relu + l-branch.
// Grid (64, 2): block (b, h-half), 512 threads = 64 h x 8 p-slices.
// 2x the blocks of the old layout -> 2x read parallelism on g_part.
// ---------------------------------------------------------------------------
__global__ __launch_bounds__(512) void finalize_kernel(
    const float* __restrict__ l, const float* __restrict__ b1,
    const float* __restrict__ W2, const float* __restrict__ b2,
    float* __restrict__ out)
{
    __shared__ float red[8][64];
    const int b    = blockIdx.x;
    const int half = blockIdx.y;
    const int tid  = threadIdx.x;
    const int hq   = tid & 63;            // h within half
    const int p    = tid >> 6;            // 0..7
    const int h    = half * 64 + hq;

    float s = 0.0f;
    #pragma unroll 18
    for (int c = p; c < NCHUNK; c += 8)
        s += g_part[(size_t)c * (B_ * HG_) + b * HG_ + h];
    red[p][hq] = s;
    __syncthreads();

    if (p == 0) {
        float v = b1[h];
        #pragma unroll
        for (int q = 0; q < 8; q++) v += red[q][hq];
        out[b * (HG_ + HL_) + h] = fmaxf(v, 0.0f);
        const float lw = l[b * 2 + 0] * W2[h] + l[b * 2 + 1] * W2[HL_ + h] + b2[h];
        out[b * (HG_ + HL_) + HG_ + h] = fmaxf(lw, 0.0f);
    }
}

// ---------------------------------------------------------------------------
extern "C" void kernel_launch(void* const* d_in, const int* in_sizes, int n_in,
                              void* d_out, int out_size)
{
    const float* x  = (const float*)d_in[0];
    const float* l  = (const float*)d_in[1];
    const float* W1 = (const float*)d_in[2];
    const float* b1 = (const float*)d_in[3];
    const float* W2 = (const float*)d_in[4];
    const float* b2 = (const float*)d_in[5];
    float* out = (float*)d_out;

    static bool attr_set = false;
    if (!attr_set) {
        cudaFuncSetAttribute(gemm_mma_kernel,
                             cudaFuncAttributeMaxDynamicSharedMemorySize, SMEM_GEMM);
        attr_set = true;
    }

    dim3 eg(32, 96);   // by<64: extract (2 windows/block); by>=64: W1 convert
    extract_kernel<<<eg, 192>>>(x, l, W1);
    gemm_mma_kernel<<<NCHUNK, 512, SMEM_GEMM>>>();
    dim3 fg(B_, 2);
    finalize_kernel<<<fg, 512>>>(l, b1, W2, b2, out);
}

// round 17
// speedup vs baseline: 1.0111x; 1.0111x over previous
#include <cuda_runtime.h>
#include <cuda_fp16.h>
#include <cstdint>

// Problem constants
#define B_     64
#define H_     512
#define W_     512
#define C_     3
#define G_     64
#define K_     3
#define D_IN   (K_*G_*G_*C_)   // 36864
#define HG_    128
#define HL_    128

// GEMM split-K config
#define NCHUNK 144
#define DC     256             // K-dims per CTA chunk (NCHUNK*DC == D_IN)

// Scratch (device globals)
__device__ __half g_phi[(size_t)B_ * D_IN];           // 4.7 MB (single fp16)
__device__ __half g_W1h[(size_t)D_IN * HG_];          // 9.4 MB (fp16 W1, [k][n])
__device__ float g_part[(size_t)NCHUNK * B_ * HG_];   // 4.7 MB

__device__ __forceinline__ uint32_t smem_u32(const void* p) {
    uint32_t a;
    asm("{ .reg .u64 t; cvta.to.shared.u64 t, %1; cvt.u32.u64 %0, t; }"
        : "=r"(a) : "l"(p));
    return a;
}
__device__ __forceinline__ void cp16(uint32_t dst, const void* src) {
    asm volatile("cp.async.cg.shared.global [%0], [%1], 16;"
                 :: "r"(dst), "l"(src) : "memory");
}
#define CP_COMMIT() asm volatile("cp.async.commit_group;" ::: "memory")

// ---------------------------------------------------------------------------
// Kernel 1: fused extraction + pooling (R15 structure — measured best 15.8us)
// + appended plain W1 fp32->fp16 convert blocks.
// Grid (64, 80): by<64 extract (b=by); by>=64 convert chunk of W1.
// ---------------------------------------------------------------------------
__global__ __launch_bounds__(192) void extract_kernel(
    const float* __restrict__ x, const float* __restrict__ l,
    const float* __restrict__ W1)
{
    const int tid = threadIdx.x;

    if (blockIdx.y >= 64) {
        // ---- W1 convert: 1024 chunks x 4608 elements ----
        const int chunk = (blockIdx.y - 64) * 64 + blockIdx.x;   // 0..1023
        const size_t base = (size_t)chunk * 4608;
        #pragma unroll
        for (int j = 0; j < 6; j++) {
            const size_t idx = base + j * 768 + tid * 4;
            const float4 v = *reinterpret_cast<const float4*>(&W1[idx]);
            __half2 p0; p0.x = __float2half_rn(v.x); p0.y = __float2half_rn(v.y);
            __half2 p1; p1.x = __float2half_rn(v.z); p1.y = __float2half_rn(v.w);
            uint2 out;
            out.x = *reinterpret_cast<uint32_t*>(&p0);
            out.y = *reinterpret_cast<uint32_t*>(&p1);
            *reinterpret_cast<uint2*>(&g_W1h[idx]) = out;
        }
        return;
    }

    __shared__ float buf[4 * 768];

    const int gy2 = blockIdx.x;
    const int b   = blockIdx.y;

    // denormalize coords exactly like reference: trunc((0.5*(l+1))*512)
    const float lx = __ldg(&l[b * 2 + 0]);
    const float ly = __ldg(&l[b * 2 + 1]);
    const int cx = (int)((0.5f * (lx + 1.0f)) * 512.0f);
    const int cy = (int)((0.5f * (ly + 1.0f)) * 512.0f);
    const int xs = cx - 128;
    const int ys = cy - 128 + gy2 * 4;

    const int jlo = (xs < 0 ? -xs : 0) * 3;
    const int xe  = xs + 256;
    const int jhi = ((xe > W_ ? W_ : xe) - xs) * 3;

    // stage 4 contiguous source rows (zero-filled OOB), scalar loads
    #pragma unroll
    for (int rr = 0; rr < 4; rr++) {
        const int y = ys + rr;
        const bool yok = (y >= 0) && (y < H_);
        const float* rowp = x + (((size_t)b * H_ + y) * W_ + xs) * C_;
        #pragma unroll
        for (int it = 0; it < 4; it++) {
            const int j = tid + it * 192;
            float v = 0.0f;
            if (yok && j >= jlo && j < jhi) v = __ldg(rowp + j);
            buf[rr * 768 + j] = v;
        }
    }
    __syncthreads();

    const int gx = tid / 3;
    const int c  = tid - gx * 3;
    const size_t phiB = (size_t)b * D_IN;

    // ---- k=2: pool 4x4 ----
    {
        float sum = 0.0f;
        #pragma unroll
        for (int dy = 0; dy < 4; dy++)
            #pragma unroll
            for (int dx = 0; dx < 4; dx++)
                sum += buf[dy * 768 + (gx * 4 + dx) * 3 + c];
        g_phi[phiB + (2 * G_ + gy2) * (G_ * C_) + tid] = __float2half_rn(sum * (1.0f / 16.0f));
    }

    // ---- k=1: two output rows, pool 2x2 over central 128 cols ----
    if (gy2 >= 16 && gy2 < 48) {
        #pragma unroll
        for (int h = 0; h < 2; h++) {
            const int gy1 = 2 * gy2 - 32 + h;
            float sum = 0.0f;
            #pragma unroll
            for (int dy = 0; dy < 2; dy++)
                #pragma unroll
                for (int dx = 0; dx < 2; dx++)
                    sum += buf[(2 * h + dy) * 768 + (64 + gx * 2 + dx) * 3 + c];
            g_phi[phiB + (G_ + gy1) * (G_ * C_) + tid] = __float2half_rn(sum * 0.25f);
        }
    }

    // ---- k=0: four output rows, direct copy of central 64 cols ----
    if (gy2 >= 24 && gy2 < 40) {
        #pragma unroll
        for (int rr = 0; rr < 4; rr++) {
            const int gy0 = 4 * gy2 - 96 + rr;
            g_phi[phiB + gy0 * (G_ * C_) + tid] =
                __float2half_rn(buf[rr * 768 + (96 + gx) * 3 + c]);
        }
    }
}

// ---------------------------------------------------------------------------
// Kernel 2: split-K GEMM via mma.sync fp16, single pass, 2-stage cp.async
// pipeline (measured best, R15). B in smem as [k][n], ldmatrix.trans.
// Grid 144, 512 threads (16 warps, warp = 16m x 32n).
// ---------------------------------------------------------------------------
#define KSTR    136                      // A: padded K stride in fp16
#define NPAD    136                      // B: padded N stride in fp16 (272B)
#define A_TILE  (64 * KSTR * 2)          // 17408 B
#define B_TILE  (128 * NPAD * 2)         // 34816 B (128 k-rows)
#define STAGE_B (A_TILE + B_TILE)        // 52224 B per stage
#define SMEM_GEMM (2 * STAGE_B)          // 104448 B

__device__ __forceinline__ void ldsm_x4(uint32_t a[4], uint32_t addr) {
    asm volatile("ldmatrix.sync.aligned.m8n8.x4.shared.b16 {%0,%1,%2,%3}, [%4];"
                 : "=r"(a[0]), "=r"(a[1]), "=r"(a[2]), "=r"(a[3]) : "r"(addr));
}
__device__ __forceinline__ void ldsm_x4t(uint32_t a[4], uint32_t addr) {
    asm volatile("ldmatrix.sync.aligned.m8n8.x4.trans.shared.b16 {%0,%1,%2,%3}, [%4];"
                 : "=r"(a[0]), "=r"(a[1]), "=r"(a[2]), "=r"(a[3]) : "r"(addr));
}
__device__ __forceinline__ void mma_fp16(
    float c[4], const uint32_t a[4], uint32_t b0, uint32_t b1)
{
    asm volatile(
        "mma.sync.aligned.m16n8k16.row.col.f32.f16.f16.f32 "
        "{%0,%1,%2,%3}, {%4,%5,%6,%7}, {%8,%9}, {%0,%1,%2,%3};"
        : "+f"(c[0]), "+f"(c[1]), "+f"(c[2]), "+f"(c[3])
        : "r"(a[0]), "r"(a[1]), "r"(a[2]), "r"(a[3]), "r"(b0), "r"(b1));
}

__global__ __launch_bounds__(512) void gemm_mma_kernel()
{
    extern __shared__ char smem[];
    const uint32_t sb = smem_u32(smem);
    const int tid  = threadIdx.x;
    const int wid  = tid >> 5;
    const int lane = tid & 31;

    const int mt = wid >> 2;     // m16 tile
    const int nq = wid & 3;      // n32 quarter

    const uint32_t aRel = (uint32_t)((mt * 16 + (lane & 15)) * (KSTR * 2)
                                     + (lane >> 4) * 16);
    const uint32_t bRel = (uint32_t)(((lane & 7) + ((lane >> 3) & 1) * 8) * (NPAD * 2)
                                     + (nq * 32 + (lane >> 4) * 8) * 2);

    const int d0 = blockIdx.x * DC;

    auto fill = [&](int stage, int dk) {
        const uint32_t base = sb + stage * STAGE_B;
        #pragma unroll
        for (int it = 0; it < 2; it++) {             // A: 64 rows x 16 chunks
            const int idx = it * 512 + tid;
            const int m = idx >> 4;
            const int i = idx & 15;
            cp16(base + m * (KSTR * 2) + i * 16,
                 &g_phi[(size_t)m * D_IN + dk + i * 8]);
        }
        #pragma unroll
        for (int it = 0; it < 4; it++) {             // B: 128 k-rows x 16 chunks
            const int idx = it * 512 + tid;
            const int k = idx >> 4;
            const int i = idx & 15;
            cp16(base + A_TILE + k * (NPAD * 2) + i * 16,
                 &g_W1h[(size_t)(dk + k) * HG_ + i * 8]);
        }
    };

    float acc[4][4];
    #pragma unroll
    for (int nt = 0; nt < 4; nt++)
        #pragma unroll
        for (int j = 0; j < 4; j++) acc[nt][j] = 0.0f;

    auto compute = [&](int stage) {
        const uint32_t base = sb + stage * STAGE_B;
        const uint32_t aBase = base + aRel;
        const uint32_t bBase = base + A_TILE + bRel;
        #pragma unroll
        for (int kt = 0; kt < 8; kt++) {
            uint32_t a[4];
            ldsm_x4(a, aBase + kt * 32);
            #pragma unroll
            for (int np = 0; np < 2; np++) {
                uint32_t bq[4];
                ldsm_x4t(bq, bBase + kt * 16 * (NPAD * 2) + np * 32);
                mma_fp16(acc[np * 2 + 0], a, bq[0], bq[1]);
                mma_fp16(acc[np * 2 + 1], a, bq[2], bq[3]);
            }
        }
    };

    // ---- 2-stage pipeline ----
    fill(0, d0);        CP_COMMIT();
    fill(1, d0 + 128);  CP_COMMIT();
    asm volatile("cp.async.wait_group 1;" ::: "memory");
    __syncthreads();
    compute(0);
    asm volatile("cp.async.wait_group 0;" ::: "memory");
    __syncthreads();
    compute(1);

    // ---- epilogue: write 64x128 partial tile ----
    float* part = &g_part[(size_t)blockIdx.x * (B_ * HG_)];
    const int qid = lane >> 2;
    const int tq  = lane & 3;
    const int row0 = mt * 16 + qid;
    #pragma unroll
    for (int nt = 0; nt < 4; nt++) {
        const int col = nq * 32 + nt * 8 + tq * 2;
        float2 v0; v0.x = acc[nt][0]; v0.y = acc[nt][1];
        float2 v1; v1.x = acc[nt][2]; v1.y = acc[nt][3];
        *reinterpret_cast<float2*>(part + row0 * HG_ + col) = v0;
        *reinterpret_cast<float2*>(part + (row0 + 8) * HG_ + col) = v1;
    }
}

// ---------------------------------------------------------------------------
// Kernel 3: reduce partials + bias + relu + l-branch.
// Grid (64, 2): block (b, h-half), 512 threads = 64 h x 8 p-slices.
// ---------------------------------------------------------------------------
__global__ __launch_bounds__(512) void finalize_kernel(
    const float* __restrict__ l, const float* __restrict__ b1,
    const float* __restrict__ W2, const float* __restrict__ b2,
    float* __restrict__ out)
{
    __shared__ float red[8][64];
    const int b    = blockIdx.x;
    const int half = blockIdx.y;
    const int tid  = threadIdx.x;
    const int hq   = tid & 63;            // h within half
    const int p    = tid >> 6;            // 0..7
    const int h    = half * 64 + hq;

    float s = 0.0f;
    #pragma unroll 18
    for (int c = p; c < NCHUNK; c += 8)
        s += g_part[(size_t)c * (B_ * HG_) + b * HG_ + h];
    red[p][hq] = s;
    __syncthreads();

    if (p == 0) {
        float v = b1[h];
        #pragma unroll
        for (int q = 0; q < 8; q++) v += red[q][hq];
        out[b * (HG_ + HL_) + h] = fmaxf(v, 0.0f);
        const float lw = l[b * 2 + 0] * W2[h] + l[b * 2 + 1] * W2[HL_ + h] + b2[h];
        out[b * (HG_ + HL_) + HG_ + h] = fmaxf(lw, 0.0f);
    }
}

// ---------------------------------------------------------------------------
extern "C" void kernel_launch(void* const* d_in, const int* in_sizes, int n_in,
                              void* d_out, int out_size)
{
    const float* x  = (const float*)d_in[0];
    const float* l  = (const float*)d_in[1];
    const float* W1 = (const float*)d_in[2];
    const float* b1 = (const float*)d_in[3];
    const float* W2 = (const float*)d_in[4];
    const float* b2 = (const float*)d_in[5];
    float* out = (float*)d_out;

    static bool attr_set = false;
    if (!attr_set) {
        cudaFuncSetAttribute(gemm_mma_kernel,
                             cudaFuncAttributeMaxDynamicSharedMemorySize, SMEM_GEMM);
        attr_set = true;
    }

    dim3 eg(G_, 80);   // by<64: extract; by>=64: W1 convert (1024 chunks)
    extract_kernel<<<eg, 192>>>(x, l, W1);
    gemm_mma_kernel<<<NCHUNK, 512, SMEM_GEMM>>>();
    dim3 fg(B_, 2);
    finalize_kernel<<<fg, 512>>>(l, b1, W2, b2, out);
}